// round 16
// baseline (speedup 1.0000x reference)
#include <cuda_runtime.h>
#include <cuda_fp16.h>
#include <stdint.h>

#define B_  16384
#define D_  4096
#define K_  14
#define QP  16

// ---- HMMA GEMM config: 128x128 CTA tile, 4 warps (2Mx2N), 64x64 warp tiles ----
#define BM 128
#define BN 128
#define BK 32
#define KTILES (D_ / BK)          // 128
#define ROWB 80                   // smem row stride bytes (32 halves + 8 pad)
#define A_STAGE (BM * ROWB)       // 10240 B
#define STAGE_BYTES (2 * A_STAGE) // A + B = 20480
#define NSTAGE 4
#define PS_BYTES (128 * QP * 4)   // 8192 B: p-hat tile [n][16]
#define GEMM_SMEM (NSTAGE * STAGE_BYTES + 512 + PS_BYTES)  // 90624 B -> 2 CTAs/SM

// ---------------- scratch (device globals; no allocations allowed) ----------
__device__ __half g_Xh [B_ * D_];
__device__ __half g_Th [B_ * D_];
__device__ __half g_Wvh[D_ * D_];
__device__ __half g_Wth[D_ * D_];
__device__ float g_phat [K_ * D_];
__device__ float g_normv[B_];
__device__ float g_normt[B_];
__device__ float g_numv [B_ * QP];
__device__ float g_numt [B_ * QP];
__device__ int   g_bcc  [K_ * K_];

// ---------------- helpers -----------------------------------------------------
__device__ __forceinline__ uint32_t smem_u32(const void* p) {
    return (uint32_t)__cvta_generic_to_shared(p);
}
__device__ __forceinline__ void cp16(uint32_t dst, const void* src) {
    asm volatile("cp.async.cg.shared.global [%0], [%1], 16;"
                 :: "r"(dst), "l"(src) : "memory");
}
__device__ __forceinline__ void cp_commit() {
    asm volatile("cp.async.commit_group;" ::: "memory");
}
template <int N>
__device__ __forceinline__ void cp_wait() {
    asm volatile("cp.async.wait_group %0;" :: "n"(N) : "memory");
}
__device__ __forceinline__ void ldsm_x4(uint32_t* r, uint32_t addr) {
    asm volatile("ldmatrix.sync.aligned.m8n8.x4.shared.b16 {%0,%1,%2,%3}, [%4];"
                 : "=r"(r[0]), "=r"(r[1]), "=r"(r[2]), "=r"(r[3]) : "r"(addr));
}
__device__ __forceinline__ void mma16816(float* c, const uint32_t* a, const uint32_t* b) {
    asm volatile(
        "mma.sync.aligned.m16n8k16.row.col.f32.f16.f16.f32 "
        "{%0,%1,%2,%3}, {%4,%5,%6,%7}, {%8,%9}, {%0,%1,%2,%3};"
        : "+f"(c[0]), "+f"(c[1]), "+f"(c[2]), "+f"(c[3])
        : "r"(a[0]), "r"(a[1]), "r"(a[2]), "r"(a[3]), "r"(b[0]), "r"(b[1]));
}

// ---------------- fp32 -> fp16 conversion (all four tensors, one launch) -------
#define N8_X  (B_ * D_ / 8)
#define N8_W  (D_ * D_ / 8)
__global__ void f2h_all(const float* __restrict__ x, const float* __restrict__ t,
                        const float* __restrict__ wv, const float* __restrict__ wt) {
    long i = (long)blockIdx.x * blockDim.x + threadIdx.x;
    const float* src;
    __half* dst;
    long j = i;
    if (j < N8_X)                 { src = x;  dst = g_Xh; }
    else if ((j -= N8_X) < N8_X)  { src = t;  dst = g_Th; }
    else if ((j -= N8_X) < N8_W)  { src = wv; dst = g_Wvh; }
    else if ((j -= N8_W) < N8_W)  { src = wt; dst = g_Wth; }
    else return;
    const float4* s4 = (const float4*)src;
    float4 a = s4[2 * j];
    float4 b = s4[2 * j + 1];
    __half2 h0 = __floats2half2_rn(a.x, a.y);
    __half2 h1 = __floats2half2_rn(a.z, a.w);
    __half2 h2 = __floats2half2_rn(b.x, b.y);
    __half2 h3 = __floats2half2_rn(b.z, b.w);
    uint4 o;
    o.x = *reinterpret_cast<uint32_t*>(&h0);
    o.y = *reinterpret_cast<uint32_t*>(&h1);
    o.z = *reinterpret_cast<uint32_t*>(&h2);
    o.w = *reinterpret_cast<uint32_t*>(&h3);
    reinterpret_cast<uint4*>(dst)[j] = o;
}

// ---------------- normalize prototypes + zero num/norm/bcc -----------------------
__global__ void phat_kernel(const float* __restrict__ proto) {
    int k = blockIdx.x, tid = threadIdx.x;
    int gt = blockIdx.x * 256 + tid;                 // 3584 global threads
    for (int i = gt; i < B_ * QP; i += K_ * 256) { g_numv[i] = 0.f; g_numt[i] = 0.f; }
    for (int i = gt; i < B_; i += K_ * 256)      { g_normv[i] = 0.f; g_normt[i] = 0.f; }
    if (gt < K_ * K_) g_bcc[gt] = 0;

    float ss = 0.f;
    for (int i = tid; i < D_; i += 256) {
        float p = proto[k * D_ + i];
        ss += p * p;
    }
    for (int off = 16; off; off >>= 1)
        ss += __shfl_xor_sync(~0u, ss, off);
    __shared__ float r0[8];
    __shared__ float s_inv;
    int warp = tid >> 5, lane = tid & 31;
    if (lane == 0) r0[warp] = ss;
    __syncthreads();
    if (tid == 0) {
        float S = 0.f;
        for (int w = 0; w < 8; w++) S += r0[w];
        s_inv = 1.0f / fmaxf(sqrtf(S), 1e-12f);
    }
    __syncthreads();
    float inv = s_inv;
    for (int i = tid; i < D_; i += 256)
        g_phat[k * D_ + i] = proto[k * D_ + i] * inv;
}

// ---------------- HMMA GEMM: row norms AND rank-14 numerator projection ----------
// y = X@W^T + bias per tile; epilogue accumulates sum(y^2) per row (norm) and
// sum_n y[b,n]*phat[k,n] per row (numerator, bias included) via atomics.
__global__ void __launch_bounds__(128, 2)
norm_gemm(const float* __restrict__ bv, const float* __restrict__ bt) {
    const int which = blockIdx.z;
    const __half* Xh = which ? g_Th : g_Xh;
    const __half* Wh = which ? g_Wth : g_Wvh;
    const float* bias = which ? bt : bv;
    float* normOut = which ? g_normt : g_normv;
    float* numOut  = which ? g_numt : g_numv;

    extern __shared__ __align__(128) char smem[];
    const uint32_t sbase = smem_u32(smem);
    float* sb = (float*)(smem + NSTAGE * STAGE_BYTES);
    float* ps = (float*)(smem + NSTAGE * STAGE_BYTES + 512);   // [128][16]

    const int tid  = threadIdx.x;
    const int lane = tid & 31;
    const int warp = tid >> 5;
    const int wm = warp & 1;
    const int wn = warp >> 1;
    const int m0 = blockIdx.y * BM;
    const int n0 = blockIdx.x * BN;

    sb[tid] = bias[n0 + tid];
    // p-hat tile: ps[n][k] (k padded to 16), n = local col
#pragma unroll
    for (int i = 0; i < 16; i++) {
        int idx = tid + i * 128;          // 2048 entries
        int n = idx >> 4, k = idx & 15;
        ps[idx] = (k < K_) ? g_phat[(size_t)k * D_ + n0 + n] : 0.f;
    }

    float acc[4][8][4];
#pragma unroll
    for (int mi = 0; mi < 4; mi++)
#pragma unroll
        for (int ni = 0; ni < 8; ni++)
#pragma unroll
            for (int c = 0; c < 4; c++) acc[mi][ni][c] = 0.f;

#define LOAD_STAGE(stage, kt)                                                  \
    {                                                                          \
        uint32_t base = sbase + (stage) * STAGE_BYTES;                         \
        int kb = (kt) * BK;                                                    \
        _Pragma("unroll")                                                      \
        for (int i = 0; i < 8; i++) {                                          \
            int idx = tid + i * 128;                                           \
            int r = (idx >> 2) & 127, c = idx & 3;                             \
            if (idx < 512)                                                     \
                cp16(base + r * ROWB + c * 16,                                 \
                     Xh + (size_t)(m0 + r) * D_ + kb + c * 8);                 \
            else                                                               \
                cp16(base + A_STAGE + r * ROWB + c * 16,                       \
                     Wh + (size_t)(n0 + r) * D_ + kb + c * 8);                 \
        }                                                                      \
        cp_commit();                                                           \
    }

    LOAD_STAGE(0, 0);
    LOAD_STAGE(1, 1);
    LOAD_STAGE(2, 2);

    const int a_r = wm * 64 + (lane & 15);
    const int a_c = (lane >> 4) << 3;
    const int b_r = wn * 64 + ((lane >> 4) << 3) + (lane & 7);
    const int b_c = ((lane >> 3) & 1) << 3;

    for (int kt = 0; kt < KTILES; ++kt) {
        cp_wait<2>();
        __syncthreads();

        const int st = kt & (NSTAGE - 1);
        const uint32_t aB = sbase + st * STAGE_BYTES;
        const uint32_t bB = aB + A_STAGE;

        uint32_t af[2][4][4], bf[2][4][4];
#pragma unroll
        for (int h = 0; h < 2; h++) {
            const int kk = h * 16;
#pragma unroll
            for (int mi = 0; mi < 4; mi++)
                ldsm_x4(af[h][mi], aB + (uint32_t)((a_r + mi * 16) * ROWB + (a_c + kk) * 2));
#pragma unroll
            for (int nj = 0; nj < 4; nj++)
                ldsm_x4(bf[h][nj], bB + (uint32_t)((b_r + nj * 16) * ROWB + (b_c + kk) * 2));
        }

        if (kt + 3 < KTILES) {
            LOAD_STAGE((kt + 3) & (NSTAGE - 1), kt + 3);
        } else {
            cp_commit();
        }

#pragma unroll
        for (int h = 0; h < 2; h++)
#pragma unroll
            for (int mi = 0; mi < 4; mi++)
#pragma unroll
                for (int nj = 0; nj < 4; nj++) {
                    mma16816(acc[mi][2 * nj],     af[h][mi], &bf[h][nj][0]);
                    mma16816(acc[mi][2 * nj + 1], af[h][mi], &bf[h][nj][2]);
                }
    }
#undef LOAD_STAGE

    // epilogue: per row, norm = sum(y^2); num[k] = sum_n y*phat[k][n]
#pragma unroll
    for (int mi = 0; mi < 4; mi++) {
        float rs0 = 0.f, rs1 = 0.f;
        float pn0[K_], pn1[K_];
#pragma unroll
        for (int k = 0; k < K_; k++) { pn0[k] = 0.f; pn1[k] = 0.f; }
#pragma unroll
        for (int ni = 0; ni < 8; ni++) {
            int nl = wn * 64 + ni * 8 + 2 * (lane & 3);
            float b0 = sb[nl], b1 = sb[nl + 1];
            float y0 = acc[mi][ni][0] + b0;
            float y1 = acc[mi][ni][1] + b1;
            float y2 = acc[mi][ni][2] + b0;
            float y3 = acc[mi][ni][3] + b1;
            rs0 += y0 * y0 + y1 * y1;
            rs1 += y2 * y2 + y3 * y3;

            const float4* p0 = (const float4*)(ps + nl * 16);
            const float4* p1 = (const float4*)(ps + (nl + 1) * 16);
            float4 a0 = p0[0], a1 = p0[1], a2 = p0[2], a3 = p0[3];
            float4 c0 = p1[0], c1 = p1[1], c2 = p1[2], c3 = p1[3];
            float pa[K_] = {a0.x, a0.y, a0.z, a0.w, a1.x, a1.y, a1.z, a1.w,
                            a2.x, a2.y, a2.z, a2.w, a3.x, a3.y};
            float pc[K_] = {c0.x, c0.y, c0.z, c0.w, c1.x, c1.y, c1.z, c1.w,
                            c2.x, c2.y, c2.z, c2.w, c3.x, c3.y};
#pragma unroll
            for (int k = 0; k < K_; k++) {
                pn0[k] += y0 * pa[k] + y1 * pc[k];
                pn1[k] += y2 * pa[k] + y3 * pc[k];
            }
        }
        // reduce across the quad (lane&3)
        rs0 += __shfl_xor_sync(~0u, rs0, 1);
        rs0 += __shfl_xor_sync(~0u, rs0, 2);
        rs1 += __shfl_xor_sync(~0u, rs1, 1);
        rs1 += __shfl_xor_sync(~0u, rs1, 2);
#pragma unroll
        for (int k = 0; k < K_; k++) {
            pn0[k] += __shfl_xor_sync(~0u, pn0[k], 1);
            pn0[k] += __shfl_xor_sync(~0u, pn0[k], 2);
            pn1[k] += __shfl_xor_sync(~0u, pn1[k], 1);
            pn1[k] += __shfl_xor_sync(~0u, pn1[k], 2);
        }
        if ((lane & 3) == 0) {
            int row = m0 + wm * 64 + mi * 16 + (lane >> 2);
            atomicAdd(&normOut[row], rs0);
            atomicAdd(&normOut[row + 8], rs1);
#pragma unroll
            for (int k = 0; k < K_; k++) {
                atomicAdd(&numOut[(size_t)row * QP + k], pn0[k]);
                atomicAdd(&numOut[(size_t)(row + 8) * QP + k], pn1[k]);
            }
        }
    }
}

// ---------------- batch co-occurrence counts --------------------------------------
__global__ void bcc_kernel(const int* __restrict__ labels) {
    __shared__ unsigned s_mask[256];
    int b = blockIdx.x * 256 + threadIdx.x;
    unsigned m = 0;
#pragma unroll
    for (int k = 0; k < K_; k++) m |= (labels[(size_t)b * K_ + k] != 0 ? 1u : 0u) << k;
    s_mask[threadIdx.x] = m;
    __syncthreads();
    if (threadIdx.x < K_ * K_) {
        int i = threadIdx.x / K_, j = threadIdx.x % K_;
        int cnt = 0;
        for (int r = 0; r < 256; ++r) {
            unsigned mm = s_mask[r];
            cnt += (int)(((mm >> i) & 1u) & ((mm >> j) & 1u));
        }
        atomicAdd(&g_bcc[threadIdx.x], cnt);
    }
}

// ---------------- finalize: shapley = 0.5*(numv/nv + numt/nt)*label ---------------
__global__ void finalize_kernel(const int* __restrict__ labels, float* __restrict__ out) {
    int idx = blockIdx.x * 256 + threadIdx.x;
    if (idx >= B_ * K_) return;
    int b = idx / K_, k = idx - b * K_;
    float nv = sqrtf(g_normv[b]);
    float nt = sqrtf(g_normt[b]);
    float vs = g_numv[(size_t)b * QP + k] / fmaxf(nv, 1e-12f);
    float ts = g_numt[(size_t)b * QP + k] / fmaxf(nt, 1e-12f);
    out[idx] = 0.5f * (vs + ts) * (float)labels[idx];
}

// ---------------- cooccur loss + prototype passthrough ------------------------------
__global__ void loss_kernel(const float* __restrict__ coocc, float* __restrict__ out_loss) {
    int t = threadIdx.x;
    float d = 0.f;
    if (t < K_ * K_) {
        float bc = (float)g_bcc[t] / (float)B_;
        float sg = 1.0f / (1.0f + expf(-coocc[t]));
        float e = sg - bc;
        d = e * e;
    }
    for (int off = 16; off; off >>= 1) d += __shfl_xor_sync(~0u, d, off);
    __shared__ float r[8];
    int warp = t >> 5, lane = t & 31;
    if (lane == 0) r[warp] = d;
    __syncthreads();
    if (t == 0) {
        float S = 0.f;
        for (int w = 0; w < 8; w++) S += r[w];
        out_loss[0] = S / (float)(K_ * K_);
    }
}

__global__ void copy_proto_kernel(const float* __restrict__ proto, float* __restrict__ dst) {
    int idx = blockIdx.x * blockDim.x + threadIdx.x;
    if (idx < K_ * D_) dst[idx] = proto[idx];
}

// ---------------- launch --------------------------------------------------------------
extern "C" void kernel_launch(void* const* d_in, const int* in_sizes, int n_in,
                              void* d_out, int out_size) {
    const float* img    = (const float*)d_in[0];
    const float* txt    = (const float*)d_in[1];
    const int*   labels = (const int*)d_in[2];
    const float* Wv     = (const float*)d_in[3];
    const float* bv     = (const float*)d_in[4];
    const float* Wt     = (const float*)d_in[5];
    const float* bt     = (const float*)d_in[6];
    const float* proto  = (const float*)d_in[7];
    const float* coocc  = (const float*)d_in[8];
    float* out = (float*)d_out;

    cudaFuncSetAttribute(norm_gemm, cudaFuncAttributeMaxDynamicSharedMemorySize,
                         GEMM_SMEM);

    phat_kernel<<<K_, 256>>>(proto);                          // 1: phat + zeroing

    long n8_total = 2L * N8_X + 2L * N8_W;
    f2h_all<<<(unsigned)((n8_total + 255) / 256), 256>>>(img, txt, Wv, Wt);  // 2

    dim3 ggrid(D_ / BN, B_ / BM, 2);   // (32, 128, 2): both GEMMs
    norm_gemm<<<ggrid, 128, GEMM_SMEM>>>(bv, bt);             // 3: norm + num fused

    bcc_kernel<<<B_ / 256, 256>>>(labels);                    // 4
    finalize_kernel<<<(B_ * K_ + 255) / 256, 256>>>(labels, out);  // 5

    if (out_size >= B_ * K_ + K_ * D_ + 1) {
        copy_proto_kernel<<<(K_ * D_ + 255) / 256, 256>>>(proto, out + (size_t)B_ * K_);
        loss_kernel<<<1, 256>>>(coocc, out + (size_t)B_ * K_ + (size_t)K_ * D_);
    }
}

// round 17
// speedup vs baseline: 1.3053x; 1.3053x over previous
#include <cuda_runtime.h>
#include <cuda_fp16.h>
#include <stdint.h>

#define B_  16384
#define D_  4096
#define K_  14
#define QP  16
#define DP  (D_ + 128)            // padded N for appended q^T tile

// ---- HMMA GEMM config: 128x128 CTA tile, 4 warps (2Mx2N), 64x64 warp tiles ----
#define BM 128
#define BN 128
#define BK 32
#define KTILES (D_ / BK)          // 128
#define ROWB 80                   // smem row stride bytes (32 halves + 8 pad)
#define A_STAGE (BM * ROWB)       // 10240 B
#define STAGE_BYTES (2 * A_STAGE) // A + B = 20480
#define NSTAGE 4
#define GEMM_SMEM (NSTAGE * STAGE_BYTES + 512)   // 82432 B -> 2 CTAs/SM

#define NUM_SMEM (2048 * 16 * 4)  // (unused slot kept for layout stability)

// ---------------- scratch (device globals; no allocations allowed) ----------
__device__ __half g_Xh [B_ * D_];
__device__ __half g_Th [B_ * D_];
__device__ __half g_Wvh[DP * D_];   // rows 0..4095 = Wv; 4096..4109 = qv^T; rest 0
__device__ __half g_Wth[DP * D_];
__device__ float g_phat [K_ * D_];
__device__ float g_qv   [D_ * QP];
__device__ float g_qt   [D_ * QP];
__device__ float g_cv   [K_];
__device__ float g_ct   [K_];
__device__ float g_normv[B_];
__device__ float g_normt[B_];
__device__ float g_numv [B_ * QP];
__device__ float g_numt [B_ * QP];
__device__ int   g_bcc  [K_ * K_];

// ---------------- helpers -----------------------------------------------------
__device__ __forceinline__ uint32_t smem_u32(const void* p) {
    return (uint32_t)__cvta_generic_to_shared(p);
}
__device__ __forceinline__ void cp16(uint32_t dst, const void* src) {
    asm volatile("cp.async.cg.shared.global [%0], [%1], 16;"
                 :: "r"(dst), "l"(src) : "memory");
}
__device__ __forceinline__ void cp_commit() {
    asm volatile("cp.async.commit_group;" ::: "memory");
}
template <int N>
__device__ __forceinline__ void cp_wait() {
    asm volatile("cp.async.wait_group %0;" :: "n"(N) : "memory");
}
__device__ __forceinline__ void ldsm_x4(uint32_t* r, uint32_t addr) {
    asm volatile("ldmatrix.sync.aligned.m8n8.x4.shared.b16 {%0,%1,%2,%3}, [%4];"
                 : "=r"(r[0]), "=r"(r[1]), "=r"(r[2]), "=r"(r[3]) : "r"(addr));
}
__device__ __forceinline__ void mma16816(float* c, const uint32_t* a, const uint32_t* b) {
    asm volatile(
        "mma.sync.aligned.m16n8k16.row.col.f32.f16.f16.f32 "
        "{%0,%1,%2,%3}, {%4,%5,%6,%7}, {%8,%9}, {%0,%1,%2,%3};"
        : "+f"(c[0]), "+f"(c[1]), "+f"(c[2]), "+f"(c[3])
        : "r"(a[0]), "r"(a[1]), "r"(a[2]), "r"(a[3]), "r"(b[0]), "r"(b[1]));
}

// ---------------- fp32 -> fp16 conversion (X, T) --------------------------------
#define N8_X  (B_ * D_ / 8)
__global__ void f2h_xt(const float* __restrict__ x, const float* __restrict__ t) {
    long i = (long)blockIdx.x * blockDim.x + threadIdx.x;
    const float* src;
    __half* dst;
    long j = i;
    if (j < N8_X)                 { src = x;  dst = g_Xh; }
    else if ((j -= N8_X) < N8_X)  { src = t;  dst = g_Th; }
    else return;
    const float4* s4 = (const float4*)src;
    float4 a = s4[2 * j];
    float4 b = s4[2 * j + 1];
    __half2 h0 = __floats2half2_rn(a.x, a.y);
    __half2 h1 = __floats2half2_rn(a.z, a.w);
    __half2 h2 = __floats2half2_rn(b.x, b.y);
    __half2 h3 = __floats2half2_rn(b.z, b.w);
    uint4 o;
    o.x = *reinterpret_cast<uint32_t*>(&h0);
    o.y = *reinterpret_cast<uint32_t*>(&h1);
    o.z = *reinterpret_cast<uint32_t*>(&h2);
    o.w = *reinterpret_cast<uint32_t*>(&h3);
    reinterpret_cast<uint4*>(dst)[j] = o;
}

// ---------------- normalize prototypes + bias dots + zeroing ---------------------
__global__ void phat_kernel(const float* __restrict__ proto,
                            const float* __restrict__ bv,
                            const float* __restrict__ bt) {
    int k = blockIdx.x, tid = threadIdx.x;
    int gt = blockIdx.x * 256 + tid;
    for (int i = gt; i < D_ * QP; i += K_ * 256) { g_qv[i] = 0.f; g_qt[i] = 0.f; }
    for (int i = gt; i < B_; i += K_ * 256)      { g_normv[i] = 0.f; g_normt[i] = 0.f; }
    if (gt < K_ * K_) g_bcc[gt] = 0;

    float ss = 0.f, sv = 0.f, st = 0.f;
    for (int i = tid; i < D_; i += 256) {
        float p = proto[k * D_ + i];
        ss += p * p; sv += p * bv[i]; st += p * bt[i];
    }
    for (int off = 16; off; off >>= 1) {
        ss += __shfl_xor_sync(~0u, ss, off);
        sv += __shfl_xor_sync(~0u, sv, off);
        st += __shfl_xor_sync(~0u, st, off);
    }
    __shared__ float r0[8], r1[8], r2[8];
    __shared__ float s_inv;
    int warp = tid >> 5, lane = tid & 31;
    if (lane == 0) { r0[warp] = ss; r1[warp] = sv; r2[warp] = st; }
    __syncthreads();
    if (tid == 0) {
        float S = 0.f, V = 0.f, T = 0.f;
        for (int w = 0; w < 8; w++) { S += r0[w]; V += r1[w]; T += r2[w]; }
        float inv = 1.0f / fmaxf(sqrtf(S), 1e-12f);
        s_inv = inv;
        g_cv[k] = V * inv;
        g_ct[k] = T * inv;
    }
    __syncthreads();
    float inv = s_inv;
    for (int i = tid; i < D_; i += 256)
        g_phat[k * D_ + i] = proto[k * D_ + i] * inv;
}

// ---------------- q = W^T @ p_hat^T (fp32 exact) + W -> fp16 staging -------------
__global__ void q_kernel(const float* __restrict__ Wv, const float* __restrict__ Wt) {
    const float* W = blockIdx.z ? Wt : Wv;
    float* q = blockIdx.z ? g_qt : g_qv;
    __half* Wh = blockIdx.z ? g_Wth : g_Wvh;
    int i  = blockIdx.x * 256 + threadIdx.x;
    int j0 = blockIdx.y * 128;
    __shared__ float ps[K_][128];
    for (int idx = threadIdx.x; idx < K_ * 128; idx += 256) {
        int k = idx >> 7, j = idx & 127;
        ps[k][j] = g_phat[k * D_ + j0 + j];
    }
    __syncthreads();
    float acc[K_];
#pragma unroll
    for (int k = 0; k < K_; k++) acc[k] = 0.f;
#pragma unroll 4
    for (int jj = 0; jj < 128; ++jj) {
        float w = W[(size_t)(j0 + jj) * D_ + i];
        Wh[(size_t)(j0 + jj) * D_ + i] = __float2half_rn(w);
#pragma unroll
        for (int k = 0; k < K_; k++) acc[k] += w * ps[k][jj];
    }
#pragma unroll
    for (int k = 0; k < K_; k++) atomicAdd(&q[i * QP + k], acc[k]);
}

// ---------------- q^T -> fp16 rows [4096..4223] of Wh (rows >= 4110 zero) --------
__global__ void q2h_kernel() {
    // 128 rows x D_ cols x 2 modalities
    int idx = blockIdx.x * 256 + threadIdx.x;
    int z = blockIdx.y;
    if (idx >= 128 * D_) return;
    int r = idx / D_, i = idx - r * D_;
    __half* Wh = z ? g_Wth : g_Wvh;
    const float* q = z ? g_qt : g_qv;
    float val = (r < K_) ? q[(size_t)i * QP + r] : 0.f;
    Wh[(size_t)(D_ + r) * D_ + i] = __float2half_rn(val);
}

// ---------------- HMMA GEMM: row norms + numerator tile (extra N-block) ----------
// grid.x = 33: x<32 -> norm tiles (sum((y+b)^2)); x==32 -> numerator tile where
// B-rows are q^T and "bias" is the bias-dot c[k]; epilogue stores y directly.
__global__ void __launch_bounds__(128, 2)
norm_gemm(const float* __restrict__ bv, const float* __restrict__ bt) {
    const int which = blockIdx.z;
    const __half* Xh = which ? g_Th : g_Xh;
    const __half* Wh = which ? g_Wth : g_Wvh;
    const float* bias = which ? bt : bv;
    const float* cvct = which ? g_ct : g_cv;
    float* normOut = which ? g_normt : g_normv;
    float* numOut  = which ? g_numt : g_numv;

    extern __shared__ __align__(128) char smem[];
    const uint32_t sbase = smem_u32(smem);
    float* sb = (float*)(smem + NSTAGE * STAGE_BYTES);

    const int tid  = threadIdx.x;
    const int lane = tid & 31;
    const int warp = tid >> 5;
    const int wm = warp & 1;
    const int wn = warp >> 1;
    const int m0 = blockIdx.y * BM;
    const int n0 = blockIdx.x * BN;
    const bool is_extra = (n0 >= D_);

    sb[tid] = is_extra ? (tid < K_ ? cvct[tid] : 0.f) : bias[n0 + tid];

    float acc[4][8][4];
#pragma unroll
    for (int mi = 0; mi < 4; mi++)
#pragma unroll
        for (int ni = 0; ni < 8; ni++)
#pragma unroll
            for (int c = 0; c < 4; c++) acc[mi][ni][c] = 0.f;

#define LOAD_STAGE(stage, kt)                                                  \
    {                                                                          \
        uint32_t base = sbase + (stage) * STAGE_BYTES;                         \
        int kb = (kt) * BK;                                                    \
        _Pragma("unroll")                                                      \
        for (int i = 0; i < 8; i++) {                                          \
            int idx = tid + i * 128;                                           \
            int r = (idx >> 2) & 127, c = idx & 3;                             \
            if (idx < 512)                                                     \
                cp16(base + r * ROWB + c * 16,                                 \
                     Xh + (size_t)(m0 + r) * D_ + kb + c * 8);                 \
            else                                                               \
                cp16(base + A_STAGE + r * ROWB + c * 16,                       \
                     Wh + (size_t)(n0 + r) * D_ + kb + c * 8);                 \
        }                                                                      \
        cp_commit();                                                           \
    }

    LOAD_STAGE(0, 0);
    LOAD_STAGE(1, 1);
    LOAD_STAGE(2, 2);

    const int a_r = wm * 64 + (lane & 15);
    const int a_c = (lane >> 4) << 3;
    const int b_r = wn * 64 + ((lane >> 4) << 3) + (lane & 7);
    const int b_c = ((lane >> 3) & 1) << 3;

    for (int kt = 0; kt < KTILES; ++kt) {
        cp_wait<2>();
        __syncthreads();

        const int st = kt & (NSTAGE - 1);
        const uint32_t aB = sbase + st * STAGE_BYTES;
        const uint32_t bB = aB + A_STAGE;

        uint32_t af[2][4][4], bf[2][4][4];
#pragma unroll
        for (int h = 0; h < 2; h++) {
            const int kk = h * 16;
#pragma unroll
            for (int mi = 0; mi < 4; mi++)
                ldsm_x4(af[h][mi], aB + (uint32_t)((a_r + mi * 16) * ROWB + (a_c + kk) * 2));
#pragma unroll
            for (int nj = 0; nj < 4; nj++)
                ldsm_x4(bf[h][nj], bB + (uint32_t)((b_r + nj * 16) * ROWB + (b_c + kk) * 2));
        }

        if (kt + 3 < KTILES) {
            LOAD_STAGE((kt + 3) & (NSTAGE - 1), kt + 3);
        } else {
            cp_commit();
        }

#pragma unroll
        for (int h = 0; h < 2; h++)
#pragma unroll
            for (int mi = 0; mi < 4; mi++)
#pragma unroll
                for (int nj = 0; nj < 4; nj++) {
                    mma16816(acc[mi][2 * nj],     af[h][mi], &bf[h][nj][0]);
                    mma16816(acc[mi][2 * nj + 1], af[h][mi], &bf[h][nj][2]);
                }
    }
#undef LOAD_STAGE

    if (!is_extra) {
        // epilogue: y = acc + bias; per-row sum of squares -> atomicAdd (R14)
#pragma unroll
        for (int mi = 0; mi < 4; mi++) {
            float rs0 = 0.f, rs1 = 0.f;
#pragma unroll
            for (int ni = 0; ni < 8; ni++) {
                int nl = wn * 64 + ni * 8 + 2 * (lane & 3);
                float b0 = sb[nl], b1 = sb[nl + 1];
                float y0 = acc[mi][ni][0] + b0;
                float y1 = acc[mi][ni][1] + b1;
                float y2 = acc[mi][ni][2] + b0;
                float y3 = acc[mi][ni][3] + b1;
                rs0 += y0 * y0 + y1 * y1;
                rs1 += y2 * y2 + y3 * y3;
            }
            rs0 += __shfl_xor_sync(~0u, rs0, 1);
            rs0 += __shfl_xor_sync(~0u, rs0, 2);
            rs1 += __shfl_xor_sync(~0u, rs1, 1);
            rs1 += __shfl_xor_sync(~0u, rs1, 2);
            if ((lane & 3) == 0) {
                int row = m0 + wm * 64 + mi * 16 + (lane >> 2);
                atomicAdd(&normOut[row], rs0);
                atomicAdd(&normOut[row + 8], rs1);
            }
        }
    } else {
        // numerator tile: columns 0..13 are num[b][k] = x.q_k + c_k. Direct store.
        if (wn == 0) {
#pragma unroll
            for (int mi = 0; mi < 4; mi++) {
#pragma unroll
                for (int ni = 0; ni < 2; ni++) {
                    int nl = ni * 8 + 2 * (lane & 3);
                    float b0 = sb[nl], b1 = sb[nl + 1];
                    int row = m0 + wm * 64 + mi * 16 + (lane >> 2);
                    numOut[(size_t)row * QP + nl]       = acc[mi][ni][0] + b0;
                    numOut[(size_t)row * QP + nl + 1]   = acc[mi][ni][1] + b1;
                    numOut[(size_t)(row + 8) * QP + nl]     = acc[mi][ni][2] + b0;
                    numOut[(size_t)(row + 8) * QP + nl + 1] = acc[mi][ni][3] + b1;
                }
            }
        }
    }
}

// ---------------- batch co-occurrence counts --------------------------------------
__global__ void bcc_kernel(const int* __restrict__ labels) {
    __shared__ unsigned s_mask[256];
    int b = blockIdx.x * 256 + threadIdx.x;
    unsigned m = 0;
#pragma unroll
    for (int k = 0; k < K_; k++) m |= (labels[(size_t)b * K_ + k] != 0 ? 1u : 0u) << k;
    s_mask[threadIdx.x] = m;
    __syncthreads();
    if (threadIdx.x < K_ * K_) {
        int i = threadIdx.x / K_, j = threadIdx.x % K_;
        int cnt = 0;
        for (int r = 0; r < 256; ++r) {
            unsigned mm = s_mask[r];
            cnt += (int)(((mm >> i) & 1u) & ((mm >> j) & 1u));
        }
        atomicAdd(&g_bcc[threadIdx.x], cnt);
    }
}

// ---------------- finalize: shapley = 0.5*(numv/nv + numt/nt)*label ---------------
__global__ void finalize_kernel(const int* __restrict__ labels, float* __restrict__ out) {
    int idx = blockIdx.x * 256 + threadIdx.x;
    if (idx >= B_ * K_) return;
    int b = idx / K_, k = idx - b * K_;
    float nv = sqrtf(g_normv[b]);
    float nt = sqrtf(g_normt[b]);
    float vs = g_numv[(size_t)b * QP + k] / fmaxf(nv, 1e-12f);
    float ts = g_numt[(size_t)b * QP + k] / fmaxf(nt, 1e-12f);
    out[idx] = 0.5f * (vs + ts) * (float)labels[idx];
}

// ---------------- cooccur loss + prototype passthrough ------------------------------
__global__ void loss_kernel(const float* __restrict__ coocc, float* __restrict__ out_loss) {
    int t = threadIdx.x;
    float d = 0.f;
    if (t < K_ * K_) {
        float bc = (float)g_bcc[t] / (float)B_;
        float sg = 1.0f / (1.0f + expf(-coocc[t]));
        float e = sg - bc;
        d = e * e;
    }
    for (int off = 16; off; off >>= 1) d += __shfl_xor_sync(~0u, d, off);
    __shared__ float r[8];
    int warp = t >> 5, lane = t & 31;
    if (lane == 0) r[warp] = d;
    __syncthreads();
    if (t == 0) {
        float S = 0.f;
        for (int w = 0; w < 8; w++) S += r[w];
        out_loss[0] = S / (float)(K_ * K_);
    }
}

__global__ void copy_proto_kernel(const float* __restrict__ proto, float* __restrict__ dst) {
    int idx = blockIdx.x * blockDim.x + threadIdx.x;
    if (idx < K_ * D_) dst[idx] = proto[idx];
}

// ---------------- launch --------------------------------------------------------------
extern "C" void kernel_launch(void* const* d_in, const int* in_sizes, int n_in,
                              void* d_out, int out_size) {
    const float* img    = (const float*)d_in[0];
    const float* txt    = (const float*)d_in[1];
    const int*   labels = (const int*)d_in[2];
    const float* Wv     = (const float*)d_in[3];
    const float* bv     = (const float*)d_in[4];
    const float* Wt     = (const float*)d_in[5];
    const float* bt     = (const float*)d_in[6];
    const float* proto  = (const float*)d_in[7];
    const float* coocc  = (const float*)d_in[8];
    float* out = (float*)d_out;

    cudaFuncSetAttribute(norm_gemm, cudaFuncAttributeMaxDynamicSharedMemorySize,
                         GEMM_SMEM);

    phat_kernel<<<K_, 256>>>(proto, bv, bt);                    // 1: phat + cv/ct + zero
    q_kernel<<<dim3(16, 32, 2), 256>>>(Wv, Wt);                 // 2: q fp32 + W->fp16
    q2h_kernel<<<dim3((128 * D_ + 255) / 256, 2), 256>>>();     // 3: q^T rows -> Wh ext
    f2h_xt<<<(unsigned)((2L * N8_X + 255) / 256), 256>>>(img, txt);  // 4: X/T -> fp16

    dim3 ggrid(DP / BN, B_ / BM, 2);   // (33, 128, 2): norm tiles + numerator tile
    norm_gemm<<<ggrid, 128, GEMM_SMEM>>>(bv, bt);               // 5

    bcc_kernel<<<B_ / 256, 256>>>(labels);                      // 6
    finalize_kernel<<<(B_ * K_ + 255) / 256, 256>>>(labels, out);  // 7

    if (out_size >= B_ * K_ + K_ * D_ + 1) {
        copy_proto_kernel<<<(K_ * D_ + 255) / 256, 256>>>(proto, out + (size_t)B_ * K_);
        loss_kernel<<<1, 256>>>(coocc, out + (size_t)B_ * K_ + (size_t)K_ * D_);
    }
}